// round 15
// baseline (speedup 1.0000x reference)
#include <cuda_runtime.h>
#include <cstdint>
#include <math.h>

#define UU 208
#define VV 176
#define NB (UU*VV)        // 36608
#define NIMG 256
#define KHALF 89          // VV/2 + 1
#define RANK 18304        // 0-indexed median index (numpy/jax 'nearest')

typedef unsigned long long ull;

// ---------------- packed f32x2 helpers -------------------------------------
__device__ __forceinline__ ull fma2(ull a, ull b, ull c) {
    ull d;
    asm("fma.rn.f32x2 %0, %1, %2, %3;" : "=l"(d) : "l"(a), "l"(b), "l"(c));
    return d;
}
__device__ __forceinline__ ull pack2(float v) {
    ull d;
    asm("mov.b64 %0, {%1, %1};" : "=l"(d) : "r"(__float_as_uint(v)));
    return d;
}
__device__ __forceinline__ float lo32(ull v) { return __uint_as_float((unsigned)(v & 0xffffffffu)); }
__device__ __forceinline__ float hi32(ull v) { return __uint_as_float((unsigned)(v >> 32)); }

// ---------------- scratch (device globals; no allocation allowed) ----------
__device__ unsigned int g_keys[NB];
__device__ unsigned int g_thr;    // key at sorted rank 18304 (percentile threshold)
__device__ float        g_h[KHALF][UU][2];        // (hr, hi) interleaved
__device__ float        g_Bv[VV][192];            // stage-A basis (192-padded)
__device__ float        g_E[2*KHALF][VV];         // stage-E basis
__device__ float        g_A[2][KHALF][UU][NIMG];  // Ar, Ai
__device__ float        g_Bb[2][KHALF][UU][NIMG]; // Br, Bi

// ---------------- K0: exact spectrum of symmetric 6x6 kernel ---------------
__global__ void k0_spectrum(const float* __restrict__ kern) {
    __shared__ double tcs[1145];
    __shared__ double p[6][6];
    for (int j = threadIdx.x; j < 1145; j += blockDim.x)
        tcs[j] = cospi((double)j / 1144.0);
    if (threadIdx.x < 36) {
        int m = threadIdx.x / 6, n = threadIdx.x % 6;
        int mm = m < 3 ? m : 5 - m;
        int nn = n < 3 ? n : 5 - n;
        p[m][n] = (double)kern[mm * 3 + nn];
    }
    __syncthreads();
    int idx = blockIdx.x * blockDim.x + threadIdx.x;
    if (idx >= NB) return;
    int l = idx / VV, k = idx % VV;
    double s = 0.0;
    for (int m = 0; m < 6; m++) {
        int tm = (13 * k * m) % 2288;
        for (int n = 0; n < 6; n++) {
            int t = (tm + 11 * l * n) % 2288;
            int tc = (t > 1144) ? (2288 - t) : t;
            s += p[m][n] * tcs[tc];
        }
    }
    float r = (float)(s / 36.0);
    unsigned u = __float_as_uint(r);
    unsigned key = (u & 0x80000000u) ? ~u : (u | 0x80000000u);
    g_keys[idx] = key;
}

// ---------------- K1: radix-select key at rank 18304 -----------------------
__global__ void k1_select() {
    __shared__ int hist[2048];
    __shared__ unsigned s_pref;
    __shared__ int s_rank;
    int tid = threadIdx.x;
    if (tid == 0) { s_pref = 0u; s_rank = RANK; }
    __syncthreads();
    for (int pass = 0; pass < 3; pass++) {
        int shift = (pass == 0) ? 21 : ((pass == 1) ? 10 : 0);
        int nbins = (pass == 2) ? 1024 : 2048;
        unsigned pmask = (pass == 0) ? 0u : ((pass == 1) ? 0xFFE00000u : 0xFFFFFC00u);
        for (int j = tid; j < 2048; j += blockDim.x) hist[j] = 0;
        __syncthreads();
        unsigned pref = s_pref;
        for (int j = tid; j < NB; j += blockDim.x) {
            unsigned key = g_keys[j];
            if ((key & pmask) == (pref & pmask)) {
                int d = (key >> shift) & (nbins - 1);
                atomicAdd(&hist[d], 1);
            }
        }
        __syncthreads();
        if (tid == 0) {
            int cum = 0, rank = s_rank;
            for (int b = 0; b < nbins; b++) {
                int c = hist[b];
                if (cum + c > rank) {
                    s_pref = pref | ((unsigned)b << shift);
                    s_rank = rank - cum;
                    break;
                }
                cum += c;
            }
        }
        __syncthreads();
    }
    if (tid == 0) g_thr = s_pref;
}

// ---------------- K2a: per-column circulant kernels h_k --------------------
// JAX's mask = strict greater-than PLUS one twin of the threshold conjugate
// pair (calibrated rounds 2..10). Hermitian representation: T-pair weight 0.5.
__global__ void k2_h() {
    int k = blockIdx.x;          // 0..88
    __shared__ float ct[UU], st[UU], wl[UU];
    int tid = threadIdx.x;
    for (int j = tid; j < UU; j += blockDim.x) {
        float sv, cv;
        sincospif(2.0f * (float)j / (float)UU, &sv, &cv);
        ct[j] = cv; st[j] = sv;
    }
    unsigned thr = g_thr;
    for (int l = tid; l < UU; l += blockDim.x) {
        unsigned key = g_keys[l * VV + k];
        wl[l] = (key > thr) ? 1.0f : ((key == thr) ? 0.5f : 0.0f);
    }
    __syncthreads();
    if (tid < UU) {
        int d = tid;
        float hr = 0.f, hi = 0.f;
        int ph = 0;
        for (int l = 0; l < UU; l++) {
            float wv = wl[l];
            hr += wv * ct[ph];
            hi += wv * st[ph];
            ph += d; if (ph >= UU) ph -= UU;
        }
        g_h[k][d][0] = hr * (1.0f / (float)UU);
        g_h[k][d][1] = hi * (1.0f / (float)UU);
    }
}

// ---------------- K2b: DFT basis matrices for stages A and E ---------------
__global__ void k2_basis() {
    int idx = blockIdx.x * blockDim.x + threadIdx.x;
    const int nBv = VV * 192;
    if (idx < nBv) {
        int n = idx / 192, c = idx % 192;
        if (c >= 178) { g_Bv[n][c] = 0.0f; return; }
        int k = c >> 1;
        int ph = (k * n) % VV;
        float s, cc;
        sincospif(2.0f * (float)ph / (float)VV, &s, &cc);
        g_Bv[n][c] = (c & 1) ? -s : cc;
    } else {
        int j = idx - nBv;
        if (j < 2 * KHALF * VV) {
            int r = j / VV, b = j % VV;
            int k = r >> 1;
            int ph = (k * b) % VV;
            float s, cc;
            sincospif(2.0f * (float)ph / (float)VV, &s, &cc);
            float ckf = (k == 0 || k == KHALF - 1) ? 1.0f : 2.0f;
            float v = (r & 1) ? (-ckf * s) : (ckf * cc);
            g_E[r][b] = v * (1.0f / (float)VV);
        }
    }
}

// ---------------- K3: stage A (V-forward), f32x2, 4c x 2imgpair ------------
// grid (208 m, 4 img-tiles), 256 threads.
// smem: Xt[176][68] float (transposed) + Bvp[176][64] u64 (duplicated-packed
// basis c-slice, 3 passes of 64 c).
__global__ __launch_bounds__(256) void k3_stageA(const float* __restrict__ x) {
    extern __shared__ float sm[];
    float* Xt = sm;                              // [176][68]
    ull* Bvp  = (ull*)(sm + 176 * 68);           // [176][64]
    int m = blockIdx.x, itile = blockIdx.y;
    int tid = threadIdx.x;
    int img0 = itile * 64;
    int cgroup = tid >> 4;                       // 0..15 -> 4 c each
    int ig = (tid & 15) << 2;                    // 4 img = 2 pairs

    for (int j = tid; j < VV * 64; j += 256) {
        int ii = j / VV, n = j - ii * VV;
        Xt[n * 68 + ii] = x[((img0 + ii) * UU + m) * VV + n];
    }

    for (int pass = 0; pass < 3; pass++) {
        int cb = pass * 64;
        for (int j = tid; j < VV * 64; j += 256) {
            int n = j >> 6, cl = j & 63;
            Bvp[j] = pack2(g_Bv[n][cb + cl]);
        }
        __syncthreads();

        ull acc[4][2];
#pragma unroll
        for (int j = 0; j < 4; j++) { acc[j][0] = 0; acc[j][1] = 0; }

        const ull* bvp = Bvp + cgroup * 4;
        const float* xtp = &Xt[ig];
#pragma unroll 4
        for (int n = 0; n < VV; n++) {
            ull b0 = bvp[n * 64 + 0];
            ull b1 = bvp[n * 64 + 1];
            ull b2 = bvp[n * 64 + 2];
            ull b3 = bvp[n * 64 + 3];
            ulonglong2 xv = *(const ulonglong2*)(xtp + n * 68);
            acc[0][0] = fma2(b0, xv.x, acc[0][0]); acc[0][1] = fma2(b0, xv.y, acc[0][1]);
            acc[1][0] = fma2(b1, xv.x, acc[1][0]); acc[1][1] = fma2(b1, xv.y, acc[1][1]);
            acc[2][0] = fma2(b2, xv.x, acc[2][0]); acc[2][1] = fma2(b2, xv.y, acc[2][1]);
            acc[3][0] = fma2(b3, xv.x, acc[3][0]); acc[3][1] = fma2(b3, xv.y, acc[3][1]);
        }

#pragma unroll
        for (int j = 0; j < 4; j++) {
            int c = cb + cgroup * 4 + j;
            if (c < 178) {
                int kk = c >> 1, ri = c & 1;
                ulonglong2 o; o.x = acc[j][0]; o.y = acc[j][1];
                *(ulonglong2*)&g_A[ri][kk][m][img0 + ig] = o;
            }
        }
        __syncthreads();
    }
}

// ---------------- K4: stage G (circulant), f32x2, 4a x 2imgpair ------------
// grid (2 a-halves[104], 4 img-tiles[64], 89 k), 416 threads.
// smem: hrp[420] u64 + hip[420] u64 (duplicated-packed, wrapped) +
//       Asr[208][64] + Asi[208][64] float.
__global__ __launch_bounds__(416) void k4_stageG() {
    extern __shared__ float sm[];
    ull* hrp = (ull*)sm;                         // [420]
    ull* hip = hrp + 420;                        // [420]
    float* Asr = (float*)(hip + 420);            // [208][64]
    float* Asi = Asr + UU * 64;                  // [208][64]
    int atile = blockIdx.x, itile = blockIdx.y, k = blockIdx.z;
    int tid = threadIdx.x;
    int img0 = itile * 64;
    int agroup = tid >> 4;                       // 0..25 -> 4 a each
    int ig = (tid & 15) << 2;                    // 4 img = 2 pairs
    int a0 = atile * 104 + agroup * 4;

    const float2* hg = (const float2*)&g_h[k][0][0];
    for (int j = tid; j < 420; j += 416) {
        int d = j; if (d >= UU) d -= UU; if (d >= UU) d -= UU;
        float2 h = hg[d];
        hrp[j] = pack2(h.x);
        hip[j] = pack2(h.y);
    }
    for (int j = tid; j < UU * 64; j += 416) {
        int mm = j >> 6, ii = j & 63;
        Asr[j] = g_A[0][k][mm][img0 + ii];
        Asi[j] = g_A[1][k][mm][img0 + ii];
    }
    __syncthreads();

    const ull SGN = 0x8000000080000000ULL;
    ull br[4][2], bi[4][2];
#pragma unroll
    for (int j = 0; j < 4; j++) { br[j][0] = br[j][1] = 0; bi[j][0] = bi[j][1] = 0; }

    int base = a0 + UU;                          // h index for m=0
#pragma unroll 2
    for (int m = 0; m < UU; m++) {
        ulonglong2 ar = *(const ulonglong2*)&Asr[(m << 6) + ig];
        ulonglong2 ai = *(const ulonglong2*)&Asi[(m << 6) + ig];
#pragma unroll
        for (int j = 0; j < 4; j++) {
            ull hr = hrp[base + j];
            ull hi = hip[base + j];
            ull hin = hi ^ SGN;
            br[j][0] = fma2(hr, ar.x, br[j][0]);  br[j][0] = fma2(hin, ai.x, br[j][0]);
            bi[j][0] = fma2(hr, ai.x, bi[j][0]);  bi[j][0] = fma2(hi,  ar.x, bi[j][0]);
            br[j][1] = fma2(hr, ar.y, br[j][1]);  br[j][1] = fma2(hin, ai.y, br[j][1]);
            bi[j][1] = fma2(hr, ai.y, bi[j][1]);  bi[j][1] = fma2(hi,  ar.y, bi[j][1]);
        }
        base--;
    }

#pragma unroll
    for (int j = 0; j < 4; j++) {
        int a = a0 + j;
        ulonglong2 o1; o1.x = br[j][0]; o1.y = br[j][1];
        ulonglong2 o2; o2.x = bi[j][0]; o2.y = bi[j][1];
        *(ulonglong2*)&g_Bb[0][k][a][img0 + ig] = o1;
        *(ulonglong2*)&g_Bb[1][k][a][img0 + ig] = o2;
    }
}

// ---------------- K5: stage E (V-inverse) + abs, f32x2, 4b x 2imgpair ------
// grid (208 a, 4 img-tiles), 256 threads.
// smem: Bsr[89][64] + Bsi[89][64] float + Esp[178][64] u64 (packed b-slice,
// 3 passes of 64 b).
__global__ __launch_bounds__(256) void k5_stageE(float* __restrict__ out) {
    extern __shared__ float sm[];
    float* Bsr = sm;                             // [89][64]
    float* Bsi = Bsr + KHALF * 64;               // [89][64]
    ull* Esp   = (ull*)(Bsi + KHALF * 64);       // [178][64]
    int a = blockIdx.x, itile = blockIdx.y;
    int tid = threadIdx.x;
    int img0 = itile * 64;
    int bgroup = tid >> 4;                       // 0..15 -> 4 b each
    int ig = (tid & 15) << 2;                    // 4 img = 2 pairs

    for (int j = tid; j < KHALF * 64; j += 256) {
        int kk = j >> 6, ii = j & 63;
        Bsr[j] = g_Bb[0][kk][a][img0 + ii];
        Bsi[j] = g_Bb[1][kk][a][img0 + ii];
    }

    for (int pass = 0; pass < 3; pass++) {
        int bb = pass * 64;
        for (int j = tid; j < 2 * KHALF * 64; j += 256) {
            int r = j >> 6, bl = j & 63;
            int b = bb + bl;
            Esp[j] = pack2((b < VV) ? g_E[r][b] : 0.f);
        }
        __syncthreads();

        ull acc[4][2];
#pragma unroll
        for (int j = 0; j < 4; j++) { acc[j][0] = 0; acc[j][1] = 0; }

        const float* bp  = &Bsr[ig];
        const float* bip = &Bsi[ig];
        const ull* ep = Esp + bgroup * 4;
#pragma unroll 2
        for (int k = 0; k < KHALF; k++) {
            ulonglong2 brv = *(const ulonglong2*)(bp + (k << 6));
            ulonglong2 biv = *(const ulonglong2*)(bip + (k << 6));
            const ull* e0 = ep + (2 * k) * 64;
            const ull* e1 = ep + (2 * k + 1) * 64;
#pragma unroll
            for (int j = 0; j < 4; j++) {
                ull e0j = e0[j], e1j = e1[j];
                acc[j][0] = fma2(brv.x, e0j, acc[j][0]);
                acc[j][0] = fma2(biv.x, e1j, acc[j][0]);
                acc[j][1] = fma2(brv.y, e0j, acc[j][1]);
                acc[j][1] = fma2(biv.y, e1j, acc[j][1]);
            }
        }

        int b0 = bb + bgroup * 4;
        if (b0 < VV) {
#pragma unroll
            for (int p = 0; p < 2; p++) {
#pragma unroll
                for (int w = 0; w < 2; w++) {
                    int img = img0 + ig + 2 * p + w;
                    float* op = &out[(img * UU + a) * VV + b0];
                    float4 o;
                    o.x = fabsf(w ? hi32(acc[0][p]) : lo32(acc[0][p]));
                    o.y = fabsf(w ? hi32(acc[1][p]) : lo32(acc[1][p]));
                    o.z = fabsf(w ? hi32(acc[2][p]) : lo32(acc[2][p]));
                    o.w = fabsf(w ? hi32(acc[3][p]) : lo32(acc[3][p]));
                    *(float4*)op = o;
                }
            }
        }
        __syncthreads();
    }
}

// ---------------- launcher -------------------------------------------------
extern "C" void kernel_launch(void* const* d_in, const int* in_sizes, int n_in,
                              void* d_out, int out_size) {
    const float* x = nullptr;
    const float* kern = nullptr;
    for (int i = 0; i < n_in; i++) {
        if (in_sizes[i] == 9) kern = (const float*)d_in[i];
        else if (in_sizes[i] > 1000) x = (const float*)d_in[i];
    }

    const int SM3 = 176 * 68 * 4 + 176 * 64 * 8;               // 137,984 B
    const int SM4 = 420 * 8 * 2 + 2 * UU * 64 * 4;             // 113,216 B
    const int SM5 = 2 * KHALF * 64 * 4 + 178 * 64 * 8;         // 136,704 B
    cudaFuncSetAttribute(k3_stageA, cudaFuncAttributeMaxDynamicSharedMemorySize, SM3);
    cudaFuncSetAttribute(k4_stageG, cudaFuncAttributeMaxDynamicSharedMemorySize, SM4);
    cudaFuncSetAttribute(k5_stageE, cudaFuncAttributeMaxDynamicSharedMemorySize, SM5);

    k0_spectrum<<<(NB + 255) / 256, 256>>>(kern);
    k1_select<<<1, 1024>>>();
    k2_h<<<KHALF, 256>>>();
    {
        int total = VV * 192 + 2 * KHALF * VV;
        k2_basis<<<(total + 255) / 256, 256>>>();
    }
    k3_stageA<<<dim3(UU, 4), 256, SM3>>>(x);
    k4_stageG<<<dim3(2, 4, KHALF), 416, SM4>>>();
    k5_stageE<<<dim3(UU, 4), 256, SM5>>>((float*)d_out);
}

// round 16
// speedup vs baseline: 1.1108x; 1.1108x over previous
#include <cuda_runtime.h>
#include <cstdint>
#include <math.h>

#define UU 208
#define VV 176
#define NB (UU*VV)        // 36608
#define NIMG 256
#define KHALF 89          // VV/2 + 1
#define RANK 18304        // 0-indexed median index (numpy/jax 'nearest')

// ---------------- scratch (device globals; no allocation allowed) ----------
__device__ unsigned int g_keys[NB];
__device__ unsigned int g_thr;    // key at sorted rank 18304 (percentile threshold)
__device__ float        g_h[KHALF][UU][2];        // (hr, hi) interleaved
__device__ float        g_Bv[VV][192];            // stage-A basis (192-padded)
__device__ float        g_E[2*KHALF][VV];         // stage-E basis
__device__ float        g_A[2][KHALF][UU][NIMG];  // Ar, Ai
__device__ float        g_Bb[2][KHALF][UU][NIMG]; // Br, Bi

// ---------------- K0: exact spectrum of symmetric 6x6 kernel ---------------
__global__ void k0_spectrum(const float* __restrict__ kern) {
    __shared__ double tcs[1145];
    __shared__ double p[6][6];
    for (int j = threadIdx.x; j < 1145; j += blockDim.x)
        tcs[j] = cospi((double)j / 1144.0);
    if (threadIdx.x < 36) {
        int m = threadIdx.x / 6, n = threadIdx.x % 6;
        int mm = m < 3 ? m : 5 - m;
        int nn = n < 3 ? n : 5 - n;
        p[m][n] = (double)kern[mm * 3 + nn];
    }
    __syncthreads();
    int idx = blockIdx.x * blockDim.x + threadIdx.x;
    if (idx >= NB) return;
    int l = idx / VV, k = idx % VV;
    double s = 0.0;
    for (int m = 0; m < 6; m++) {
        int tm = (13 * k * m) % 2288;
        for (int n = 0; n < 6; n++) {
            int t = (tm + 11 * l * n) % 2288;
            int tc = (t > 1144) ? (2288 - t) : t;
            s += p[m][n] * tcs[tc];
        }
    }
    float r = (float)(s / 36.0);
    unsigned u = __float_as_uint(r);
    unsigned key = (u & 0x80000000u) ? ~u : (u | 0x80000000u);
    g_keys[idx] = key;
}

// ---------------- K1: radix-select key at rank 18304 -----------------------
__global__ void k1_select() {
    __shared__ int hist[2048];
    __shared__ unsigned s_pref;
    __shared__ int s_rank;
    int tid = threadIdx.x;
    if (tid == 0) { s_pref = 0u; s_rank = RANK; }
    __syncthreads();
    for (int pass = 0; pass < 3; pass++) {
        int shift = (pass == 0) ? 21 : ((pass == 1) ? 10 : 0);
        int nbins = (pass == 2) ? 1024 : 2048;
        unsigned pmask = (pass == 0) ? 0u : ((pass == 1) ? 0xFFE00000u : 0xFFFFFC00u);
        for (int j = tid; j < 2048; j += blockDim.x) hist[j] = 0;
        __syncthreads();
        unsigned pref = s_pref;
        for (int j = tid; j < NB; j += blockDim.x) {
            unsigned key = g_keys[j];
            if ((key & pmask) == (pref & pmask)) {
                int d = (key >> shift) & (nbins - 1);
                atomicAdd(&hist[d], 1);
            }
        }
        __syncthreads();
        if (tid == 0) {
            int cum = 0, rank = s_rank;
            for (int b = 0; b < nbins; b++) {
                int c = hist[b];
                if (cum + c > rank) {
                    s_pref = pref | ((unsigned)b << shift);
                    s_rank = rank - cum;
                    break;
                }
                cum += c;
            }
        }
        __syncthreads();
    }
    if (tid == 0) g_thr = s_pref;
}

// ---------------- K2 (fused): h_k circulant kernels + DFT bases ------------
// blocks 0..88: per-column circulant kernel h_k. JAX's mask = strict
// greater-than PLUS one twin of the threshold conjugate pair (calibrated
// rounds 2..10): Hermitian representation = T-pair weight 0.5.
// blocks 89..: basis matrices g_Bv / g_E.
__global__ void k2_fused() {
    if (blockIdx.x < KHALF) {
        int k = blockIdx.x;
        __shared__ float ct[UU], st[UU], wl[UU];
        int tid = threadIdx.x;
        for (int j = tid; j < UU; j += blockDim.x) {
            float sv, cv;
            sincospif(2.0f * (float)j / (float)UU, &sv, &cv);
            ct[j] = cv; st[j] = sv;
        }
        unsigned thr = g_thr;
        for (int l = tid; l < UU; l += blockDim.x) {
            unsigned key = g_keys[l * VV + k];
            wl[l] = (key > thr) ? 1.0f : ((key == thr) ? 0.5f : 0.0f);
        }
        __syncthreads();
        if (tid < UU) {
            int d = tid;
            float hr = 0.f, hi = 0.f;
            int ph = 0;
            for (int l = 0; l < UU; l++) {
                float wv = wl[l];
                hr += wv * ct[ph];
                hi += wv * st[ph];
                ph += d; if (ph >= UU) ph -= UU;
            }
            g_h[k][d][0] = hr * (1.0f / (float)UU);
            g_h[k][d][1] = hi * (1.0f / (float)UU);
        }
    } else {
        int idx = (blockIdx.x - KHALF) * blockDim.x + threadIdx.x;
        const int nBv = VV * 192;
        if (idx < nBv) {
            int n = idx / 192, c = idx % 192;
            if (c >= 178) { g_Bv[n][c] = 0.0f; return; }
            int k = c >> 1;
            int ph = (k * n) % VV;
            float s, cc;
            sincospif(2.0f * (float)ph / (float)VV, &s, &cc);
            g_Bv[n][c] = (c & 1) ? -s : cc;
        } else {
            int j = idx - nBv;
            if (j < 2 * KHALF * VV) {
                int r = j / VV, b = j % VV;
                int k = r >> 1;
                int ph = (k * b) % VV;
                float s, cc;
                sincospif(2.0f * (float)ph / (float)VV, &s, &cc);
                float ckf = (k == 0 || k == KHALF - 1) ? 1.0f : 2.0f;
                float v = (r & 1) ? (-ckf * s) : (ckf * cc);
                g_E[r][b] = v * (1.0f / (float)VV);
            }
        }
    }
}

// ---------------- K3: stage A (V-forward), 4c x 4img register tile ---------
// grid (208 m, 4 img-tiles), 256 threads.
// smem: Xt[176][68] (transposed, padded) + Bvs[176][64] (c-slice per pass)
__global__ __launch_bounds__(256, 2) void k3_stageA(const float* __restrict__ x) {
    extern __shared__ float sm[];
    float* Xt  = sm;                  // [176][68]
    float* Bvs = sm + 176 * 68;       // [176][64]
    int m = blockIdx.x, itile = blockIdx.y;
    int tid = threadIdx.x;
    int img0 = itile * 64;
    int cgroup = tid >> 4;            // 0..15 -> 4 c each
    int ig = (tid & 15) << 2;         // 0..60 -> 4 img

    for (int j = tid; j < VV * 64; j += 256) {
        int ii = j / VV, n = j - ii * VV;
        Xt[n * 68 + ii] = x[((img0 + ii) * UU + m) * VV + n];
    }

    for (int pass = 0; pass < 3; pass++) {
        int cb = pass * 64;
        for (int j = tid; j < VV * 64; j += 256) {
            int n = j >> 6, cl = j & 63;
            Bvs[j] = g_Bv[n][cb + cl];
        }
        __syncthreads();

        float acc[4][4];
#pragma unroll
        for (int j = 0; j < 4; j++)
#pragma unroll
            for (int t = 0; t < 4; t++) acc[j][t] = 0.f;

        const float* bvp = &Bvs[cgroup * 4];
        const float* xtp = &Xt[ig];
#pragma unroll 4
        for (int n = 0; n < VV; n++) {
            float4 bv = *(const float4*)(bvp + n * 64);
            float4 xv = *(const float4*)(xtp + n * 68);
#pragma unroll
            for (int t = 0; t < 4; t++) {
                acc[0][t] += bv.x * ((const float*)&xv)[t];
                acc[1][t] += bv.y * ((const float*)&xv)[t];
                acc[2][t] += bv.z * ((const float*)&xv)[t];
                acc[3][t] += bv.w * ((const float*)&xv)[t];
            }
        }

#pragma unroll
        for (int j = 0; j < 4; j++) {
            int c = cb + cgroup * 4 + j;
            if (c < 178) {
                int kk = c >> 1, ri = c & 1;
                *(float4*)&g_A[ri][kk][m][img0 + ig] =
                    make_float4(acc[j][0], acc[j][1], acc[j][2], acc[j][3]);
            }
        }
        __syncthreads();
    }
}

// ---------------- K4: stage G (circulant), 4a x 4img, 32-img tile ----------
// grid (8 img-tiles[32], 89 k), 416 threads (52 a-groups x 8 img-groups).
// smem: h2[420] float2 (wrapped) + Asr[208][32] + Asi[208][32]  (~56.6 KB
// -> 2 blocks/SM, 832 thr/SM: 2x the occupancy of the 64-img variant).
// Per-accumulator arithmetic order identical to the 669us champion.
__global__ __launch_bounds__(416, 2) void k4_stageG() {
    extern __shared__ float sm[];
    float2* h2 = (float2*)sm;              // [420]
    float* Asr = sm + 840;                 // [208][32]
    float* Asi = Asr + UU * 32;            // [208][32]
    int itile = blockIdx.x, k = blockIdx.y;
    int tid = threadIdx.x;
    int img0 = itile * 32;
    int agroup = tid >> 3;                 // 0..51 -> 4 a each
    int ig = (tid & 7) << 2;               // 4 img
    int a0 = agroup * 4;

    const float2* hg = (const float2*)&g_h[k][0][0];
    for (int j = tid; j < 420; j += 416) {
        int d = j; if (d >= UU) d -= UU; if (d >= UU) d -= UU;
        h2[j] = hg[d];
    }
    for (int j = tid; j < UU * 32; j += 416) {
        int mm = j >> 5, ii = j & 31;
        Asr[j] = g_A[0][k][mm][img0 + ii];
        Asi[j] = g_A[1][k][mm][img0 + ii];
    }
    __syncthreads();

    float br[4][4], bi[4][4];
#pragma unroll
    for (int j = 0; j < 4; j++)
#pragma unroll
        for (int t = 0; t < 4; t++) { br[j][t] = 0.f; bi[j][t] = 0.f; }

    int base = a0 + UU;                    // h index for m=0
#pragma unroll 2
    for (int m = 0; m < UU; m++) {
        float2 h0 = h2[base + 0];
        float2 h1 = h2[base + 1];
        float2 h2v = h2[base + 2];
        float2 h3 = h2[base + 3];
        float4 ar = *(const float4*)&Asr[(m << 5) + ig];
        float4 ai = *(const float4*)&Asi[(m << 5) + ig];
        const float* arp = (const float*)&ar;
        const float* aip = (const float*)&ai;
#pragma unroll
        for (int t = 0; t < 4; t++) {
            float arv = arp[t], aiv = aip[t];
            br[0][t] += h0.x * arv - h0.y * aiv;  bi[0][t] += h0.x * aiv + h0.y * arv;
            br[1][t] += h1.x * arv - h1.y * aiv;  bi[1][t] += h1.x * aiv + h1.y * arv;
            br[2][t] += h2v.x * arv - h2v.y * aiv; bi[2][t] += h2v.x * aiv + h2v.y * arv;
            br[3][t] += h3.x * arv - h3.y * aiv;  bi[3][t] += h3.x * aiv + h3.y * arv;
        }
        base--;
    }

#pragma unroll
    for (int j = 0; j < 4; j++) {
        int a = a0 + j;
        *(float4*)&g_Bb[0][k][a][img0 + ig] =
            make_float4(br[j][0], br[j][1], br[j][2], br[j][3]);
        *(float4*)&g_Bb[1][k][a][img0 + ig] =
            make_float4(bi[j][0], bi[j][1], bi[j][2], bi[j][3]);
    }
}

// ---------------- K5: stage E (V-inverse) + abs, 4b x 4img tile ------------
// grid (208 a, 4 img-tiles), 256 threads.
// smem: Bsr[89][64] + Bsi[89][64] + Ess[178][64] (b-slice per pass)
__global__ __launch_bounds__(256, 2) void k5_stageE(float* __restrict__ out) {
    extern __shared__ float sm[];
    float* Bsr = sm;                        // [89][64]
    float* Bsi = Bsr + KHALF * 64;          // [89][64]
    float* Ess = Bsi + KHALF * 64;          // [178][64]
    int a = blockIdx.x, itile = blockIdx.y;
    int tid = threadIdx.x;
    int img0 = itile * 64;
    int bgroup = tid >> 4;                  // 0..15 -> 4 b each
    int ig = (tid & 15) << 2;               // 4 img

    for (int j = tid; j < KHALF * 64; j += 256) {
        int kk = j >> 6, ii = j & 63;
        Bsr[j] = g_Bb[0][kk][a][img0 + ii];
        Bsi[j] = g_Bb[1][kk][a][img0 + ii];
    }

    for (int pass = 0; pass < 3; pass++) {
        int bb = pass * 64;
        for (int j = tid; j < 2 * KHALF * 64; j += 256) {
            int r = j >> 6, bl = j & 63;
            Ess[j] = (bb + bl < VV) ? g_E[r][bb + bl] : 0.f;
        }
        __syncthreads();

        float acc[4][4];
#pragma unroll
        for (int j = 0; j < 4; j++)
#pragma unroll
            for (int t = 0; t < 4; t++) acc[j][t] = 0.f;

        const float* bp = &Bsr[ig];
        const float* bip = &Bsi[ig];
        const float* ep = &Ess[bgroup * 4];
#pragma unroll 2
        for (int k = 0; k < KHALF; k++) {
            float4 brv = *(const float4*)(bp + (k << 6));
            float4 biv = *(const float4*)(bip + (k << 6));
            float4 e0 = *(const float4*)(ep + (2 * k) * 64);
            float4 e1 = *(const float4*)(ep + (2 * k + 1) * 64);
            const float* brp = (const float*)&brv;
            const float* bipp = (const float*)&biv;
            const float* e0p = (const float*)&e0;
            const float* e1p = (const float*)&e1;
#pragma unroll
            for (int j = 0; j < 4; j++)
#pragma unroll
                for (int t = 0; t < 4; t++)
                    acc[j][t] += brp[t] * e0p[j] + bipp[t] * e1p[j];
        }

        int b0 = bb + bgroup * 4;
        if (b0 < VV) {
#pragma unroll
            for (int t = 0; t < 4; t++) {
                int img = img0 + ig + t;
                float* op = &out[(img * UU + a) * VV + b0];
                op[0] = fabsf(acc[0][t]);
                op[1] = fabsf(acc[1][t]);
                op[2] = fabsf(acc[2][t]);
                op[3] = fabsf(acc[3][t]);
            }
        }
        __syncthreads();
    }
}

// ---------------- launcher -------------------------------------------------
extern "C" void kernel_launch(void* const* d_in, const int* in_sizes, int n_in,
                              void* d_out, int out_size) {
    const float* x = nullptr;
    const float* kern = nullptr;
    for (int i = 0; i < n_in; i++) {
        if (in_sizes[i] == 9) kern = (const float*)d_in[i];
        else if (in_sizes[i] > 1000) x = (const float*)d_in[i];
    }

    const int SM3 = (176 * 68 + 176 * 64) * 4;                 // 92,928 B
    const int SM4 = (840 + 2 * UU * 32) * 4;                   // 56,576 B
    const int SM5 = (2 * KHALF * 64 + 2 * KHALF * 64) * 4;     // 91,136 B
    cudaFuncSetAttribute(k3_stageA, cudaFuncAttributeMaxDynamicSharedMemorySize, SM3);
    cudaFuncSetAttribute(k4_stageG, cudaFuncAttributeMaxDynamicSharedMemorySize, SM4);
    cudaFuncSetAttribute(k5_stageE, cudaFuncAttributeMaxDynamicSharedMemorySize, SM5);

    k0_spectrum<<<(NB + 255) / 256, 256>>>(kern);
    k1_select<<<1, 1024>>>();
    {
        int total = VV * 192 + 2 * KHALF * VV;
        int basisBlocks = (total + 255) / 256;
        k2_fused<<<KHALF + basisBlocks, 256>>>();
    }
    k3_stageA<<<dim3(UU, 4), 256, SM3>>>(x);
    k4_stageG<<<dim3(8, KHALF), 416, SM4>>>();
    k5_stageE<<<dim3(UU, 4), 256, SM5>>>((float*)d_out);
}

// round 17
// speedup vs baseline: 1.3018x; 1.1719x over previous
#include <cuda_runtime.h>
#include <cstdint>
#include <math.h>

#define UU 208
#define UH 104
#define VV 176
#define NB (UU*VV)        // 36608
#define NIMG 256
#define KHALF 89          // VV/2 + 1
#define RANK 18304        // 0-indexed median index (numpy/jax 'nearest')

// ---------------- scratch (device globals; no allocation allowed) ----------
__device__ unsigned int g_keys[NB];
__device__ unsigned int g_thr;    // key at sorted rank 18304 (percentile threshold)
__device__ float        g_he[KHALF][UH][2];       // even-weight circulant kernel
__device__ float        g_ho[KHALF][UH][2];       // odd-weight circulant kernel
__device__ float        g_Bv[VV][192];            // stage-A basis (192-padded)
__device__ float        g_E[2*KHALF][VV];         // stage-E basis
__device__ float        g_A[2][KHALF][UU][NIMG];  // Ar, Ai (full 208)
__device__ float        g_Af[2][2][KHALF][UH][NIMG]; // folded [eo][ri]
__device__ float        g_Bb2[2][2][KHALF][UH][NIMG]; // Bev/Bod [eo][ri]

// ---------------- K0: exact spectrum of symmetric 6x6 kernel ---------------
__global__ void k0_spectrum(const float* __restrict__ kern) {
    __shared__ double tcs[1145];
    __shared__ double p[6][6];
    for (int j = threadIdx.x; j < 1145; j += blockDim.x)
        tcs[j] = cospi((double)j / 1144.0);
    if (threadIdx.x < 36) {
        int m = threadIdx.x / 6, n = threadIdx.x % 6;
        int mm = m < 3 ? m : 5 - m;
        int nn = n < 3 ? n : 5 - n;
        p[m][n] = (double)kern[mm * 3 + nn];
    }
    __syncthreads();
    int idx = blockIdx.x * blockDim.x + threadIdx.x;
    if (idx >= NB) return;
    int l = idx / VV, k = idx % VV;
    double s = 0.0;
    for (int m = 0; m < 6; m++) {
        int tm = (13 * k * m) % 2288;
        for (int n = 0; n < 6; n++) {
            int t = (tm + 11 * l * n) % 2288;
            int tc = (t > 1144) ? (2288 - t) : t;
            s += p[m][n] * tcs[tc];
        }
    }
    float r = (float)(s / 36.0);
    unsigned u = __float_as_uint(r);
    unsigned key = (u & 0x80000000u) ? ~u : (u | 0x80000000u);
    g_keys[idx] = key;
}

// ---------------- K1: radix-select key at rank 18304 -----------------------
__global__ void k1_select() {
    __shared__ int hist[2048];
    __shared__ unsigned s_pref;
    __shared__ int s_rank;
    int tid = threadIdx.x;
    if (tid == 0) { s_pref = 0u; s_rank = RANK; }
    __syncthreads();
    for (int pass = 0; pass < 3; pass++) {
        int shift = (pass == 0) ? 21 : ((pass == 1) ? 10 : 0);
        int nbins = (pass == 2) ? 1024 : 2048;
        unsigned pmask = (pass == 0) ? 0u : ((pass == 1) ? 0xFFE00000u : 0xFFFFFC00u);
        for (int j = tid; j < 2048; j += blockDim.x) hist[j] = 0;
        __syncthreads();
        unsigned pref = s_pref;
        for (int j = tid; j < NB; j += blockDim.x) {
            unsigned key = g_keys[j];
            if ((key & pmask) == (pref & pmask)) {
                int d = (key >> shift) & (nbins - 1);
                atomicAdd(&hist[d], 1);
            }
        }
        __syncthreads();
        if (tid == 0) {
            int cum = 0, rank = s_rank;
            for (int b = 0; b < nbins; b++) {
                int c = hist[b];
                if (cum + c > rank) {
                    s_pref = pref | ((unsigned)b << shift);
                    s_rank = rank - cum;
                    break;
                }
                cum += c;
            }
        }
        __syncthreads();
    }
    if (tid == 0) g_thr = s_pref;
}

// ---------------- K2 (fused): he/ho circulant kernels + DFT bases ----------
// blocks 0..88: radix-2-split circulant kernels.
//   he(d) = (1/208) sum_s w[2s]   e^{2pi i s d/104}
//   ho(d) = (1/208) sum_s w[2s+1] e^{2pi i s d/104}
// Weight rule (calibrated rounds 2..10): strict greater-than, threshold
// conjugate pair gets 0.5 (Hermitian half of JAX's one-twin-included mask).
// blocks 89..: basis matrices g_Bv / g_E.
__global__ void k2_fused() {
    if (blockIdx.x < KHALF) {
        int k = blockIdx.x;
        __shared__ float ct[UH], st[UH], wl[UU];
        int tid = threadIdx.x;
        for (int j = tid; j < UH; j += blockDim.x) {
            float sv, cv;
            sincospif(2.0f * (float)j / (float)UH, &sv, &cv);
            ct[j] = cv; st[j] = sv;
        }
        unsigned thr = g_thr;
        for (int l = tid; l < UU; l += blockDim.x) {
            unsigned key = g_keys[l * VV + k];
            wl[l] = (key > thr) ? 1.0f : ((key == thr) ? 0.5f : 0.0f);
        }
        __syncthreads();
        if (tid < UH) {
            int d = tid;
            float her = 0.f, hei = 0.f, hor = 0.f, hoi = 0.f;
            int ph = 0;
            for (int s = 0; s < UH; s++) {
                float we = wl[2 * s], wo = wl[2 * s + 1];
                float c = ct[ph], si = st[ph];
                her += we * c; hei += we * si;
                hor += wo * c; hoi += wo * si;
                ph += d; if (ph >= UH) ph -= UH;
            }
            const float inv = 1.0f / (float)UU;
            g_he[k][d][0] = her * inv; g_he[k][d][1] = hei * inv;
            g_ho[k][d][0] = hor * inv; g_ho[k][d][1] = hoi * inv;
        }
    } else {
        int idx = (blockIdx.x - KHALF) * blockDim.x + threadIdx.x;
        const int nBv = VV * 192;
        if (idx < nBv) {
            int n = idx / 192, c = idx % 192;
            if (c >= 178) { g_Bv[n][c] = 0.0f; return; }
            int k = c >> 1;
            int ph = (k * n) % VV;
            float s, cc;
            sincospif(2.0f * (float)ph / (float)VV, &s, &cc);
            g_Bv[n][c] = (c & 1) ? -s : cc;
        } else {
            int j = idx - nBv;
            if (j < 2 * KHALF * VV) {
                int r = j / VV, b = j % VV;
                int k = r >> 1;
                int ph = (k * b) % VV;
                float s, cc;
                sincospif(2.0f * (float)ph / (float)VV, &s, &cc);
                float ckf = (k == 0 || k == KHALF - 1) ? 1.0f : 2.0f;
                float v = (r & 1) ? (-ckf * s) : (ckf * cc);
                g_E[r][b] = v * (1.0f / (float)VV);
            }
        }
    }
}

// ---------------- K3: stage A (V-forward), 4c x 4img register tile ---------
__global__ __launch_bounds__(256, 2) void k3_stageA(const float* __restrict__ x) {
    extern __shared__ float sm[];
    float* Xt  = sm;                  // [176][68]
    float* Bvs = sm + 176 * 68;       // [176][64]
    int m = blockIdx.x, itile = blockIdx.y;
    int tid = threadIdx.x;
    int img0 = itile * 64;
    int cgroup = tid >> 4;            // 0..15 -> 4 c each
    int ig = (tid & 15) << 2;         // 0..60 -> 4 img

    for (int j = tid; j < VV * 64; j += 256) {
        int ii = j / VV, n = j - ii * VV;
        Xt[n * 68 + ii] = x[((img0 + ii) * UU + m) * VV + n];
    }

    for (int pass = 0; pass < 3; pass++) {
        int cb = pass * 64;
        for (int j = tid; j < VV * 64; j += 256) {
            int n = j >> 6, cl = j & 63;
            Bvs[j] = g_Bv[n][cb + cl];
        }
        __syncthreads();

        float acc[4][4];
#pragma unroll
        for (int j = 0; j < 4; j++)
#pragma unroll
            for (int t = 0; t < 4; t++) acc[j][t] = 0.f;

        const float* bvp = &Bvs[cgroup * 4];
        const float* xtp = &Xt[ig];
#pragma unroll 4
        for (int n = 0; n < VV; n++) {
            float4 bv = *(const float4*)(bvp + n * 64);
            float4 xv = *(const float4*)(xtp + n * 68);
#pragma unroll
            for (int t = 0; t < 4; t++) {
                acc[0][t] += bv.x * ((const float*)&xv)[t];
                acc[1][t] += bv.y * ((const float*)&xv)[t];
                acc[2][t] += bv.z * ((const float*)&xv)[t];
                acc[3][t] += bv.w * ((const float*)&xv)[t];
            }
        }

#pragma unroll
        for (int j = 0; j < 4; j++) {
            int c = cb + cgroup * 4 + j;
            if (c < 178) {
                int kk = c >> 1, ri = c & 1;
                *(float4*)&g_A[ri][kk][m][img0 + ig] =
                    make_float4(acc[j][0], acc[j][1], acc[j][2], acc[j][3]);
            }
        }
        __syncthreads();
    }
}

// ---------------- K3b: radix-2 fold of A along m ---------------------------
// Ae[m] = A[m] + A[m+104]
// Ao[m] = (A[m] - A[m+104]) * e^{-2pi i m/208}
__global__ void k3b_fold() {
    int m = blockIdx.x;      // 0..103
    int k = blockIdx.y;      // 0..88
    int img = threadIdx.x;   // 0..255
    float ar0 = g_A[0][k][m][img],      ai0 = g_A[1][k][m][img];
    float ar1 = g_A[0][k][m + UH][img], ai1 = g_A[1][k][m + UH][img];
    float st, ct;
    sincospif((float)m / (float)UH, &st, &ct);   // angle 2*pi*m/208 = pi*m/104
    float tr = ar0 - ar1, ti = ai0 - ai1;
    g_Af[0][0][k][m][img] = ar0 + ar1;
    g_Af[0][1][k][m][img] = ai0 + ai1;
    g_Af[1][0][k][m][img] = tr * ct + ti * st;   // (tr+i ti)(ct - i st)
    g_Af[1][1][k][m][img] = ti * ct - tr * st;
}

// ---------------- K4: stage G = two half-size complex circulants -----------
// grid (2 eo, 4 img-tiles[64], 89 k), 416 threads, 4a x 4img tile.
// smem: h2[212] float2 (wrapped) + Asr[104][64] + Asi[104][64]  (~55 KB,
// 2 blocks/SM). Same inner-loop shape as the 669us champion, half length.
__global__ __launch_bounds__(416, 2) void k4_stageG() {
    extern __shared__ float sm[];
    float2* h2 = (float2*)sm;              // [212]
    float* Asr = sm + 424;                 // [104][64]
    float* Asi = Asr + UH * 64;            // [104][64]
    int eo = blockIdx.x, itile = blockIdx.y, k = blockIdx.z;
    int tid = threadIdx.x;
    int img0 = itile * 64;
    int agroup = tid >> 4;                 // 0..25 -> 4 a each
    int ig = (tid & 15) << 2;              // 4 img
    int a0 = agroup * 4;

    const float2* hg = (const float2*)(eo ? &g_ho[k][0][0] : &g_he[k][0][0]);
    for (int j = tid; j < 212; j += 416) {
        int d = j; if (d >= UH) d -= UH; if (d >= UH) d -= UH;
        h2[j] = hg[d];
    }
    for (int j = tid; j < UH * 64; j += 416) {
        int mm = j >> 6, ii = j & 63;
        Asr[j] = g_Af[eo][0][k][mm][img0 + ii];
        Asi[j] = g_Af[eo][1][k][mm][img0 + ii];
    }
    __syncthreads();

    float br[4][4], bi[4][4];
#pragma unroll
    for (int j = 0; j < 4; j++)
#pragma unroll
        for (int t = 0; t < 4; t++) { br[j][t] = 0.f; bi[j][t] = 0.f; }

    int base = a0 + UH;                    // h index for m=0
#pragma unroll 2
    for (int m = 0; m < UH; m++) {
        float2 h0 = h2[base + 0];
        float2 h1 = h2[base + 1];
        float2 h2v = h2[base + 2];
        float2 h3 = h2[base + 3];
        float4 ar = *(const float4*)&Asr[(m << 6) + ig];
        float4 ai = *(const float4*)&Asi[(m << 6) + ig];
        const float* arp = (const float*)&ar;
        const float* aip = (const float*)&ai;
#pragma unroll
        for (int t = 0; t < 4; t++) {
            float arv = arp[t], aiv = aip[t];
            br[0][t] += h0.x * arv - h0.y * aiv;  bi[0][t] += h0.x * aiv + h0.y * arv;
            br[1][t] += h1.x * arv - h1.y * aiv;  bi[1][t] += h1.x * aiv + h1.y * arv;
            br[2][t] += h2v.x * arv - h2v.y * aiv; bi[2][t] += h2v.x * aiv + h2v.y * arv;
            br[3][t] += h3.x * arv - h3.y * aiv;  bi[3][t] += h3.x * aiv + h3.y * arv;
        }
        base--;
    }

#pragma unroll
    for (int j = 0; j < 4; j++) {
        int a = a0 + j;
        *(float4*)&g_Bb2[eo][0][k][a][img0 + ig] =
            make_float4(br[j][0], br[j][1], br[j][2], br[j][3]);
        *(float4*)&g_Bb2[eo][1][k][a][img0 + ig] =
            make_float4(bi[j][0], bi[j][1], bi[j][2], bi[j][3]);
    }
}

// ---------------- K5: butterfly + stage E (V-inverse) + abs ----------------
// B[a] = Bev[a'] + sg*omega(a')*Bod[a'],  a'=a mod 104, sg=+1/-1,
// omega = e^{2pi i a'/208}. Butterfly folded into the smem loader.
__global__ __launch_bounds__(256, 2) void k5_stageE(float* __restrict__ out) {
    extern __shared__ float sm[];
    float* Bsr = sm;                        // [89][64]
    float* Bsi = Bsr + KHALF * 64;          // [89][64]
    float* Ess = Bsi + KHALF * 64;          // [178][64]
    int a = blockIdx.x, itile = blockIdx.y;
    int tid = threadIdx.x;
    int img0 = itile * 64;
    int bgroup = tid >> 4;                  // 0..15 -> 4 b each
    int ig = (tid & 15) << 2;               // 4 img

    int ah = (a < UH) ? a : (a - UH);
    float sg = (a < UH) ? 1.0f : -1.0f;
    float sph, cph;
    sincospif((float)ah / (float)UH, &sph, &cph);  // angle 2*pi*ah/208
    float wr = sg * cph, wi = sg * sph;

    for (int j = tid; j < KHALF * 64; j += 256) {
        int kk = j >> 6, ii = j & 63;
        float evr = g_Bb2[0][0][kk][ah][img0 + ii];
        float evi = g_Bb2[0][1][kk][ah][img0 + ii];
        float odr = g_Bb2[1][0][kk][ah][img0 + ii];
        float odi = g_Bb2[1][1][kk][ah][img0 + ii];
        Bsr[j] = evr + wr * odr - wi * odi;
        Bsi[j] = evi + wr * odi + wi * odr;
    }

    for (int pass = 0; pass < 3; pass++) {
        int bb = pass * 64;
        for (int j = tid; j < 2 * KHALF * 64; j += 256) {
            int r = j >> 6, bl = j & 63;
            Ess[j] = (bb + bl < VV) ? g_E[r][bb + bl] : 0.f;
        }
        __syncthreads();

        float acc[4][4];
#pragma unroll
        for (int j = 0; j < 4; j++)
#pragma unroll
            for (int t = 0; t < 4; t++) acc[j][t] = 0.f;

        const float* bp = &Bsr[ig];
        const float* bip = &Bsi[ig];
        const float* ep = &Ess[bgroup * 4];
#pragma unroll 2
        for (int k = 0; k < KHALF; k++) {
            float4 brv = *(const float4*)(bp + (k << 6));
            float4 biv = *(const float4*)(bip + (k << 6));
            float4 e0 = *(const float4*)(ep + (2 * k) * 64);
            float4 e1 = *(const float4*)(ep + (2 * k + 1) * 64);
            const float* brp = (const float*)&brv;
            const float* bipp = (const float*)&biv;
            const float* e0p = (const float*)&e0;
            const float* e1p = (const float*)&e1;
#pragma unroll
            for (int j = 0; j < 4; j++)
#pragma unroll
                for (int t = 0; t < 4; t++)
                    acc[j][t] += brp[t] * e0p[j] + bipp[t] * e1p[j];
        }

        int b0 = bb + bgroup * 4;
        if (b0 < VV) {
#pragma unroll
            for (int t = 0; t < 4; t++) {
                int img = img0 + ig + t;
                float* op = &out[(img * UU + a) * VV + b0];
                op[0] = fabsf(acc[0][t]);
                op[1] = fabsf(acc[1][t]);
                op[2] = fabsf(acc[2][t]);
                op[3] = fabsf(acc[3][t]);
            }
        }
        __syncthreads();
    }
}

// ---------------- launcher -------------------------------------------------
extern "C" void kernel_launch(void* const* d_in, const int* in_sizes, int n_in,
                              void* d_out, int out_size) {
    const float* x = nullptr;
    const float* kern = nullptr;
    for (int i = 0; i < n_in; i++) {
        if (in_sizes[i] == 9) kern = (const float*)d_in[i];
        else if (in_sizes[i] > 1000) x = (const float*)d_in[i];
    }

    const int SM3 = (176 * 68 + 176 * 64) * 4;                 // 92,928 B
    const int SM4 = (424 + 2 * UH * 64) * 4;                   // 54,944 B
    const int SM5 = (2 * KHALF * 64 + 2 * KHALF * 64) * 4;     // 91,136 B
    cudaFuncSetAttribute(k3_stageA, cudaFuncAttributeMaxDynamicSharedMemorySize, SM3);
    cudaFuncSetAttribute(k4_stageG, cudaFuncAttributeMaxDynamicSharedMemorySize, SM4);
    cudaFuncSetAttribute(k5_stageE, cudaFuncAttributeMaxDynamicSharedMemorySize, SM5);

    k0_spectrum<<<(NB + 255) / 256, 256>>>(kern);
    k1_select<<<1, 1024>>>();
    {
        int total = VV * 192 + 2 * KHALF * VV;
        int basisBlocks = (total + 255) / 256;
        k2_fused<<<KHALF + basisBlocks, 256>>>();
    }
    k3_stageA<<<dim3(UU, 4), 256, SM3>>>(x);
    k3b_fold<<<dim3(UH, KHALF), 256>>>();
    k4_stageG<<<dim3(2, 4, KHALF), 416, SM4>>>();
    k5_stageE<<<dim3(UU, 4), 256, SM5>>>((float*)d_out);
}